// round 6
// baseline (speedup 1.0000x reference)
#include <cuda_runtime.h>
#include <math.h>
#include <stddef.h>

#define H 100
#define HM 50            // H/2 (k-pairs)
#define HMH 25           // k-pairs per half
#define G 400            // 4*H
#define BATCH 512
#define TT 1024
#define FF 64
#define NTOK (BATCH * TT)        // 524288
#define RPB 4                    // batch rows per LSTM CTA
#define LSTM_CTAS (BATCH / RPB)  // 128
#define LSTM_THREADS 800         // (column, k-half) per thread
#define GEMM_ROWS 32
#define GEMM_THREADS 400
#define AS_STRIDE 40             // padded [k][row] stride for pregemm (160B)

typedef unsigned long long u64;

// Scratch (static device allocation: no cudaMalloc allowed)
__device__ float g_xw[(size_t)NTOK * G];   // 838.9 MB, reused by both layers
__device__ float g_h1[(size_t)NTOK * H];   // 209.7 MB
__device__ float g_h2last[BATCH * H];

// ---------------------------------------------------------------------------
// f32x2 packed-FMA helpers (sm_100+)
// ---------------------------------------------------------------------------
__device__ __forceinline__ u64 f2dup(float x)
{
    u64 r;
    asm("mov.b64 %0, {%1, %1};" : "=l"(r) : "f"(x));
    return r;
}
__device__ __forceinline__ u64 f2pack(float lo, float hi)
{
    u64 r;
    asm("mov.b64 %0, {%1, %2};" : "=l"(r) : "f"(lo), "f"(hi));
    return r;
}
__device__ __forceinline__ void fma2(u64& d, u64 a, u64 b)
{
    asm("fma.rn.f32x2 %0, %1, %2, %0;" : "+l"(d) : "l"(a), "l"(b));
}
__device__ __forceinline__ float2 unpk(u64 v)
{
    float2 r;
    asm("mov.b64 {%0, %1}, %2;" : "=f"(r.x), "=f"(r.y) : "l"(v));
    return r;
}

// ---------------------------------------------------------------------------
// Fast transcendentals: MUFU ex2/rcp (abs err ~1e-6, far under 1e-3 budget)
// ---------------------------------------------------------------------------
#define LOG2E 1.4426950408889634f
__device__ __forceinline__ float ex2a(float x)
{
    float r;
    asm("ex2.approx.f32 %0, %1;" : "=f"(r) : "f"(x));
    return r;
}
__device__ __forceinline__ float rcpa(float x)
{
    float r;
    asm("rcp.approx.f32 %0, %1;" : "=f"(r) : "f"(x));
    return r;
}
__device__ __forceinline__ float fast_sig(float x)
{
    return rcpa(1.f + ex2a(-x * LOG2E));             // 1/(1+e^-x)
}
__device__ __forceinline__ float fast_tanh(float x)
{
    // tanh(x) = 2*sigmoid(2x) - 1
    return fmaf(2.f, rcpa(1.f + ex2a(-2.f * LOG2E * x)), -1.f);
}

// ---------------------------------------------------------------------------
// Pre-activation GEMM: out[N,400] = A[N,K] @ Wm[K,400] + bias
// ROWS=32, 2 CTAs/SM. k unrolled x4 with 4-deep W prefetch to cover the
// ~39cyc L1-hit LDG latency. Per k: dup + 8 bcast LDS.128 + 16 FFMA2.
// ---------------------------------------------------------------------------
template <int K>
__global__ void __launch_bounds__(GEMM_THREADS, 2)
pregemm_kernel(const float* __restrict__ A, const float* __restrict__ Wm,
               const float* __restrict__ bias, float* __restrict__ out)
{
    __shared__ __align__(16) float A_s[K * AS_STRIDE];
    const int tid = threadIdx.x;
    const size_t row0 = (size_t)blockIdx.x * GEMM_ROWS;

    const float* Atile = A + row0 * K;
    for (int i = tid; i < GEMM_ROWS * K; i += GEMM_THREADS) {
        const int r = i / K;
        const int k = i % K;
        A_s[k * AS_STRIDE + r] = Atile[i];
    }
    __syncthreads();

    const int c = tid;
    u64 acc[GEMM_ROWS / 2];
#pragma unroll
    for (int p = 0; p < GEMM_ROWS / 2; ++p) acc[p] = 0ull;

    static_assert(K % 4 == 0, "K divisible by 4");
    float w[4];
#pragma unroll
    for (int i = 0; i < 4; ++i) w[i] = Wm[i * G + c];

    for (int k = 0; k < K; k += 4) {
        float wn[4];
        if (k + 4 < K) {
#pragma unroll
            for (int i = 0; i < 4; ++i) wn[i] = Wm[(k + 4 + i) * G + c];
        }
#pragma unroll
        for (int i = 0; i < 4; ++i) {
            const u64 wd = f2dup(w[i]);
            const float* ak = &A_s[(k + i) * AS_STRIDE];
#pragma unroll
            for (int q = 0; q < GEMM_ROWS / 4; ++q) {
                const ulonglong2 a = *(const ulonglong2*)(ak + q * 4);
                fma2(acc[q * 2 + 0], a.x, wd);
                fma2(acc[q * 2 + 1], a.y, wd);
            }
        }
#pragma unroll
        for (int i = 0; i < 4; ++i) w[i] = wn[i];
    }

    const float bc = bias[c];
#pragma unroll
    for (int p = 0; p < GEMM_ROWS / 2; ++p) {
        const float2 v = unpk(acc[p]);
        out[(row0 + 2 * p + 0) * G + c] = v.x + bc;
        out[(row0 + 2 * p + 1) * G + c] = v.y + bc;
    }
}

// ---------------------------------------------------------------------------
// Persistent LSTM layer: one CTA owns RPB=4 batch rows for all T steps.
// 800 threads = (k-half, column), 25 U k-pairs in registers per thread.
// Matvec inner loop explicitly software-pipelined: h(m+1) loads issue while
// h(m) FMAs execute, so the 29cyc LDS latency is covered.
// ---------------------------------------------------------------------------
template <bool STORE_ALL>
__global__ void __launch_bounds__(LSTM_THREADS, 1)
lstm_kernel(const float* __restrict__ zpre,   // [B,T,G]
            const float* __restrict__ U,      // [H,G]
            float* __restrict__ h_all,        // [B,T,H] (layer 1)
            float* __restrict__ h_last)       // [B,H]   (layer 2)
{
    __shared__ __align__(16) u64 h2_s[HM * RPB];   // [m][r] packed k-pairs
    __shared__ float z_s[2 * RPB * G];             // [half][r][c]

    const int tid  = threadIdx.x;              // 0..799
    const int b0   = blockIdx.x * RPB;
    const int half = tid / G;                  // k-half (0 or 1)
    const int c    = tid % G;                  // column
    const int hbase = half * HMH * RPB;        // h2_s offset for this half
    const int row  = tid / H;                  // gate row (tid<400)
    const int j    = tid % H;                  // gate hidden index

    // 25 U k-pairs for this (half, c) into registers
    u64 U_pk[HMH];
#pragma unroll
    for (int m = 0; m < HMH; ++m) {
        const int k0 = 2 * (half * HMH + m);
        U_pk[m] = f2pack(U[k0 * G + c], U[(k0 + 1) * G + c]);
    }

    if (tid < HM * RPB) h2_s[tid] = 0ull;

    float cs = 0.f, hv = 0.f;
    __syncthreads();

    const size_t bstride = (size_t)TT * G;
    const float* zp = zpre + (size_t)b0 * bstride + c;

    // step-0 pre-activation prefetch (half 0 only; half 1 contributes 0)
    float zr0 = 0.f, zr1 = 0.f, zr2 = 0.f, zr3 = 0.f;
    if (half == 0) {
        zr0 = zp[0];
        zr1 = zp[bstride];
        zr2 = zp[2 * bstride];
        zr3 = zp[3 * bstride];
    }

    for (int t = 0; t < TT; ++t) {
        u64 a0 = 0ull, a1 = 0ull, a2 = 0ull, a3 = 0ull;

        // software-pipelined matvec: prefetch h(m+1) while FMAing h(m)
        ulonglong2 hA = *(const ulonglong2*)&h2_s[hbase];       // rows 0,1
        ulonglong2 hB = *(const ulonglong2*)&h2_s[hbase + 2];   // rows 2,3
#pragma unroll
        for (int m = 0; m < HMH; ++m) {
            ulonglong2 nA, nB;
            if (m + 1 < HMH) {
                nA = *(const ulonglong2*)&h2_s[hbase + (m + 1) * RPB];
                nB = *(const ulonglong2*)&h2_s[hbase + (m + 1) * RPB + 2];
            }
            fma2(a0, hA.x, U_pk[m]);
            fma2(a1, hA.y, U_pk[m]);
            fma2(a2, hB.x, U_pk[m]);
            fma2(a3, hB.y, U_pk[m]);
            if (m + 1 < HMH) { hA = nA; hB = nB; }
        }
        const float2 s0 = unpk(a0);
        const float2 s1 = unpk(a1);
        const float2 s2 = unpk(a2);
        const float2 s3 = unpk(a3);
        float* zh = z_s + half * (RPB * G);
        zh[0 * G + c] = (s0.x + s0.y) + zr0;
        zh[1 * G + c] = (s1.x + s1.y) + zr1;
        zh[2 * G + c] = (s2.x + s2.y) + zr2;
        zh[3 * G + c] = (s3.x + s3.y) + zr3;

        // prefetch next step's pre-activations (half 0)
        if (half == 0 && t + 1 < TT) {
            zp += G;
            zr0 = zp[0];
            zr1 = zp[bstride];
            zr2 = zp[2 * bstride];
            zr3 = zp[3 * bstride];
        }
        __syncthreads();

        // gate phase: threads 0..399 own one (row, j)
        if (tid < RPB * H) {
            const float zi = z_s[row * G + j]         + z_s[RPB * G + row * G + j];
            const float zf = z_s[row * G + H + j]     + z_s[RPB * G + row * G + H + j];
            const float zg = z_s[row * G + 2 * H + j] + z_s[RPB * G + row * G + 2 * H + j];
            const float zo = z_s[row * G + 3 * H + j] + z_s[RPB * G + row * G + 3 * H + j];
            const float ig = fast_sig(zi);
            const float fg = fast_sig(zf);
            const float gg = fast_tanh(zg);
            const float og = fast_sig(zo);
            cs = fmaf(fg, cs, ig * gg);
            hv = og * fast_tanh(cs);
            ((float*)h2_s)[((j >> 1) * RPB + row) * 2 + (j & 1)] = hv;
            if (STORE_ALL)
                h_all[((size_t)(b0 + row) * TT + t) * H + j] = hv;
        }
        __syncthreads();
    }

    if (!STORE_ALL && tid < RPB * H)
        h_last[(b0 + row) * H + j] = hv;
}

// ---------------------------------------------------------------------------
// Final dense + sigmoid
// ---------------------------------------------------------------------------
__global__ void dense_kernel(const float* __restrict__ h_last,
                             const float* __restrict__ Wd,
                             const float* __restrict__ bd,
                             float* __restrict__ out)
{
    const int b = blockIdx.x * blockDim.x + threadIdx.x;
    if (b >= BATCH) return;
    float s = bd[0];
#pragma unroll
    for (int k = 0; k < H; ++k)
        s = fmaf(h_last[b * H + k], Wd[k], s);
    out[b] = 1.f / (1.f + __expf(-s));
}

// ---------------------------------------------------------------------------
extern "C" void kernel_launch(void* const* d_in, const int* in_sizes, int n_in,
                              void* d_out, int out_size)
{
    const float* x  = (const float*)d_in[0];
    const float* W1 = (const float*)d_in[1];
    const float* U1 = (const float*)d_in[2];
    const float* b1 = (const float*)d_in[3];
    const float* W2 = (const float*)d_in[4];
    const float* U2 = (const float*)d_in[5];
    const float* b2 = (const float*)d_in[6];
    const float* Wd = (const float*)d_in[7];
    const float* bd = (const float*)d_in[8];
    float* out = (float*)d_out;

    float *xw, *h1, *h2l;
    cudaGetSymbolAddress((void**)&xw,  g_xw);
    cudaGetSymbolAddress((void**)&h1,  g_h1);
    cudaGetSymbolAddress((void**)&h2l, g_h2last);

    // Layer 1
    pregemm_kernel<FF><<<NTOK / GEMM_ROWS, GEMM_THREADS>>>(x, W1, b1, xw);
    lstm_kernel<true><<<LSTM_CTAS, LSTM_THREADS>>>(xw, U1, h1, nullptr);
    // Layer 2
    pregemm_kernel<H><<<NTOK / GEMM_ROWS, GEMM_THREADS>>>(h1, W2, b2, xw);
    lstm_kernel<false><<<LSTM_CTAS, LSTM_THREADS>>>(xw, U2, nullptr, h2l);
    // Head
    dense_kernel<<<2, 256>>>(h2l, Wd, bd, out);
}